// round 1
// baseline (speedup 1.0000x reference)
#include <cuda_runtime.h>
#include <math.h>

// Problem constants (fixed by the dataset)
#define D_DIM 182
#define H_DIM 218
#define W_DIM 182
#define EMBED_DIM 768
#define REGION_MAX 116

// Combined transform M = inv(aal_affine) @ mri_affine, row-major 4x4.
__device__ float g_M[16];

// --- Prep: invert aal_affine (4x4 Gauss-Jordan w/ partial pivoting), fuse with mri_affine.
__global__ void prep_kernel(const float* __restrict__ mri, const float* __restrict__ aal) {
    if (threadIdx.x != 0 || blockIdx.x != 0) return;
    float a[4][8];
    for (int i = 0; i < 4; i++)
        for (int j = 0; j < 4; j++) {
            a[i][j] = aal[i * 4 + j];
            a[i][j + 4] = (i == j) ? 1.0f : 0.0f;
        }
    for (int c = 0; c < 4; c++) {
        int p = c;
        float best = fabsf(a[c][c]);
        for (int r = c + 1; r < 4; r++) {
            float v = fabsf(a[r][c]);
            if (v > best) { best = v; p = r; }
        }
        if (p != c) {
            for (int j = 0; j < 8; j++) { float t = a[c][j]; a[c][j] = a[p][j]; a[p][j] = t; }
        }
        float inv = 1.0f / a[c][c];
        for (int j = 0; j < 8; j++) a[c][j] *= inv;
        for (int r = 0; r < 4; r++) {
            if (r == c) continue;
            float f = a[r][c];
            for (int j = 0; j < 8; j++) a[r][j] -= f * a[c][j];
        }
    }
    // M = inv(aal) * mri
    for (int i = 0; i < 4; i++)
        for (int j = 0; j < 4; j++) {
            float s = 0.0f;
            for (int k = 0; k < 4; k++) s += a[i][k + 4] * mri[k * 4 + j];
            g_M[i * 4 + j] = s;
        }
}

// --- Main: one warp per point. Lane 0 computes region id, warp copies the 768-float row.
__global__ __launch_bounds__(256) void embed_kernel(
    const float* __restrict__ centers,   // [total, 3]
    const float* __restrict__ aal_data,  // [D,H,W]
    const float* __restrict__ table,     // [117, 768]
    float* __restrict__ out,             // [total, 768]
    int total)
{
    int gwarp = (int)((blockIdx.x * blockDim.x + threadIdx.x) >> 5);
    int lane = threadIdx.x & 31;
    if (gwarp >= total) return;

    int region = 0;
    if (lane == 0) {
        float x0 = centers[gwarp * 3 + 0];
        float y0 = centers[gwarp * 3 + 1];
        float z0 = centers[gwarp * 3 + 2];
        float X = g_M[0] * x0 + g_M[1] * y0 + g_M[2]  * z0 + g_M[3];
        float Y = g_M[4] * x0 + g_M[5] * y0 + g_M[6]  * z0 + g_M[7];
        float Z = g_M[8] * x0 + g_M[9] * y0 + g_M[10] * z0 + g_M[11];
        int xi = (int)rintf(X);   // round-half-even, matches jnp.round
        int yi = (int)rintf(Y);
        int zi = (int)rintf(Z);
        bool inb = (xi >= 0) & (xi < D_DIM) & (yi >= 0) & (yi < H_DIM) & (zi >= 0) & (zi < W_DIM);
        int cx = min(max(xi, 0), D_DIM - 1);
        int cy = min(max(yi, 0), H_DIM - 1);
        int cz = min(max(zi, 0), W_DIM - 1);
        int r = (int)aal_data[((size_t)cx * H_DIM + cy) * W_DIM + cz];
        region = (inb && r >= 0 && r <= REGION_MAX) ? r : 0;
    }
    region = __shfl_sync(0xffffffffu, region, 0);

    const float4* __restrict__ src = (const float4*)(table + (size_t)region * EMBED_DIM);
    float4* __restrict__ dst = (float4*)(out + (size_t)gwarp * EMBED_DIM);
    #pragma unroll
    for (int i = 0; i < EMBED_DIM / 4 / 32; i++) {   // 6 iterations
        dst[lane + 32 * i] = src[lane + 32 * i];
    }
}

extern "C" void kernel_launch(void* const* d_in, const int* in_sizes, int n_in,
                              void* d_out, int out_size) {
    const float* centers = (const float*)d_in[0];  // patch_centers_voxels [B,N,3]
    const float* mri     = (const float*)d_in[1];  // mri_affine [4,4]
    const float* aal     = (const float*)d_in[2];  // aal_affine [4,4]
    const float* atlas   = (const float*)d_in[3];  // aal_data [D,H,W]
    const float* table   = (const float*)d_in[4];  // embed_table [117,768]
    float* out = (float*)d_out;

    int total = in_sizes[0] / 3;  // B*N points

    prep_kernel<<<1, 32>>>(mri, aal);

    const int threads = 256;                 // 8 warps -> 8 points per block
    int warps_per_block = threads / 32;
    int blocks = (total + warps_per_block - 1) / warps_per_block;
    embed_kernel<<<blocks, threads>>>(centers, atlas, table, out, total);
}

// round 2
// speedup vs baseline: 1.0114x; 1.0114x over previous
#include <cuda_runtime.h>
#include <math.h>

#define D_DIM 182
#define H_DIM 218
#define W_DIM 182
#define EMBED_DIM 768
#define REGION_MAX 116

#define PTS_PER_BLOCK 64
#define THREADS 256            // 8 warps; each warp copies 8 rows

__global__ __launch_bounds__(THREADS) void embed_kernel(
    const float* __restrict__ centers,   // [total, 3]
    const float* __restrict__ mri,       // [4,4]
    const float* __restrict__ aal,       // [4,4]
    const float* __restrict__ aal_data,  // [D,H,W]
    const float* __restrict__ table,     // [117, 768]
    float* __restrict__ out,             // [total, 768]
    int total)
{
    __shared__ float sM[12];                 // rows 0..2 of inv(aal)*mri (row 3 unused)
    __shared__ int   sRegion[PTS_PER_BLOCK];

    const int tid = threadIdx.x;
    const int base = blockIdx.x * PTS_PER_BLOCK;

    // ---- Phase 0: thread 0 computes combined transform (redundant per block, ~200 flops)
    if (tid == 0) {
        float a[4][8];
        #pragma unroll
        for (int i = 0; i < 4; i++)
            #pragma unroll
            for (int j = 0; j < 4; j++) {
                a[i][j] = aal[i * 4 + j];
                a[i][j + 4] = (i == j) ? 1.0f : 0.0f;
            }
        #pragma unroll
        for (int c = 0; c < 4; c++) {
            int p = c;
            float best = fabsf(a[c][c]);
            for (int r = c + 1; r < 4; r++) {
                float v = fabsf(a[r][c]);
                if (v > best) { best = v; p = r; }
            }
            if (p != c) {
                for (int j = 0; j < 8; j++) { float t = a[c][j]; a[c][j] = a[p][j]; a[p][j] = t; }
            }
            float inv = 1.0f / a[c][c];
            for (int j = 0; j < 8; j++) a[c][j] *= inv;
            for (int r = 0; r < 4; r++) {
                if (r == c) continue;
                float f = a[r][c];
                for (int j = 0; j < 8; j++) a[r][j] -= f * a[c][j];
            }
        }
        // M = inv(aal) * mri, need only first 3 rows
        #pragma unroll
        for (int i = 0; i < 3; i++)
            #pragma unroll
            for (int j = 0; j < 4; j++) {
                float s = 0.0f;
                #pragma unroll
                for (int k = 0; k < 4; k++) s += a[i][k + 4] * mri[k * 4 + j];
                sM[i * 4 + j] = s;
            }
    }
    __syncthreads();

    // ---- Phase 1: 64 parallel region lookups (one per thread, independent gathers)
    if (tid < PTS_PER_BLOCK) {
        int pt = base + tid;
        int region = 0;
        if (pt < total) {
            float x0 = centers[pt * 3 + 0];
            float y0 = centers[pt * 3 + 1];
            float z0 = centers[pt * 3 + 2];
            float X = sM[0] * x0 + sM[1] * y0 + sM[2]  * z0 + sM[3];
            float Y = sM[4] * x0 + sM[5] * y0 + sM[6]  * z0 + sM[7];
            float Z = sM[8] * x0 + sM[9] * y0 + sM[10] * z0 + sM[11];
            int xi = (int)rintf(X);   // round-half-even, matches jnp.round
            int yi = (int)rintf(Y);
            int zi = (int)rintf(Z);
            bool inb = (xi >= 0) & (xi < D_DIM) & (yi >= 0) & (yi < H_DIM) &
                       (zi >= 0) & (zi < W_DIM);
            int cx = min(max(xi, 0), D_DIM - 1);
            int cy = min(max(yi, 0), H_DIM - 1);
            int cz = min(max(zi, 0), W_DIM - 1);
            int r = (int)__ldg(&aal_data[((size_t)cx * H_DIM + cy) * W_DIM + cz]);
            region = (inb && r >= 0 && r <= REGION_MAX) ? r : 0;
        }
        sRegion[tid] = region;
    }
    __syncthreads();

    // ---- Phase 2: stream copy. Warp w copies rows w, w+8, ..., w+56.
    const int warp = tid >> 5;
    const int lane = tid & 31;
    const int warps = THREADS / 32;   // 8

    #pragma unroll
    for (int i = 0; i < PTS_PER_BLOCK / (THREADS / 32); i++) {   // 8 points per warp
        int p = warp + i * warps;
        int pt = base + p;
        if (pt >= total) break;
        int region = sRegion[p];
        const float4* __restrict__ src = (const float4*)(table + (size_t)region * EMBED_DIM);
        float4* __restrict__ dst = (float4*)(out + (size_t)pt * EMBED_DIM);
        float4 v0 = __ldg(&src[lane]);
        float4 v1 = __ldg(&src[lane + 32]);
        float4 v2 = __ldg(&src[lane + 64]);
        float4 v3 = __ldg(&src[lane + 96]);
        float4 v4 = __ldg(&src[lane + 128]);
        float4 v5 = __ldg(&src[lane + 160]);
        dst[lane]       = v0;
        dst[lane + 32]  = v1;
        dst[lane + 64]  = v2;
        dst[lane + 96]  = v3;
        dst[lane + 128] = v4;
        dst[lane + 160] = v5;
    }
}

extern "C" void kernel_launch(void* const* d_in, const int* in_sizes, int n_in,
                              void* d_out, int out_size) {
    const float* centers = (const float*)d_in[0];  // patch_centers_voxels [B,N,3]
    const float* mri     = (const float*)d_in[1];  // mri_affine [4,4]
    const float* aal     = (const float*)d_in[2];  // aal_affine [4,4]
    const float* atlas   = (const float*)d_in[3];  // aal_data [D,H,W]
    const float* table   = (const float*)d_in[4];  // embed_table [117,768]
    float* out = (float*)d_out;

    int total = in_sizes[0] / 3;  // B*N points
    int blocks = (total + PTS_PER_BLOCK - 1) / PTS_PER_BLOCK;

    embed_kernel<<<blocks, THREADS>>>(centers, mri, aal, atlas, table, out, total);
}